// round 14
// baseline (speedup 1.0000x reference)
#include <cuda_runtime.h>

#define NN      256
#define DD      64
#define NH      4
#define DHD     32
#define NINNER  128
#define NOUT    516   // 384 qkv + 128 gate + 4 bias
#define ATT_SCALE 0.17677669529663687f  // 1/sqrt(32)

// ---------------- scratch (device globals: sanctioned, no runtime alloc) ----
__device__ float g_q   [NN*NH*NN*DHD];   // [n][h][c][d]
__device__ float g_k   [NN*NH*NN*DHD];
__device__ float g_v   [NN*NH*NN*DHD];
__device__ float g_gate[NN*NN*NINNER];   // [n][i][e], post-sigmoid
__device__ float g_bias[NH*NN*NN];       // [h][i][j]
__device__ float g_ao  [NN*NN*NINNER];   // attn-out * gate
__device__ int   g_flags[2];             // [0]=swap ln pair, [1]=mask mode (0=f32,1=i32,2=u8)

// ---------------- packed f32x2 helpers (FFMA2: 2 MACs per issue) ------------
typedef unsigned long long ull;

__device__ __forceinline__ void ffma2(ull& d, ull a, ull b) {
    asm volatile("fma.rn.f32x2 %0, %1, %2, %0;" : "+l"(d) : "l"(a), "l"(b));
}
__device__ __forceinline__ ull addf2(ull a, ull b) {
    ull r; asm("add.rn.f32x2 %0, %1, %2;" : "=l"(r) : "l"(a), "l"(b)); return r;
}
__device__ __forceinline__ ull pack2(float lo, float hi) {
    ull r; asm("mov.b64 %0, {%1, %2};" : "=l"(r) : "f"(lo), "f"(hi)); return r;
}
__device__ __forceinline__ float2 unpack2(ull v) {
    float2 r; asm("mov.b64 {%0, %1}, %2;" : "=f"(r.x), "=f"(r.y) : "l"(v)); return r;
}
__device__ __forceinline__ float hsum2(ull a) { float2 f = unpack2(a); return f.x + f.y; }

// ---------------- kernel 0: resolve input ambiguities on-device -------------
__global__ void detect_kernel(const float* __restrict__ lnA,
                              const float* __restrict__ lnB,
                              const unsigned int* __restrict__ mask_w)
{
    __shared__ int sA, sB, sFloat, sInt;
    if (threadIdx.x == 0) { sA = 1; sB = 1; sFloat = 1; sInt = 1; }
    __syncthreads();
    if (threadIdx.x < 64) {
        if (lnA[threadIdx.x] != 1.0f) atomicAnd(&sA, 0);
        if (lnB[threadIdx.x] != 1.0f) atomicAnd(&sB, 0);
    }
    for (int i = threadIdx.x; i < 4096; i += 256) {
        unsigned int w = mask_w[i];
        if (w != 0u && w != 0x3F800000u) atomicAnd(&sFloat, 0);
        if (w > 1u)                       atomicAnd(&sInt, 0);
    }
    __syncthreads();
    if (threadIdx.x == 0) {
        g_flags[0] = (!sA && sB) ? 1 : 0;
        g_flags[1] = sFloat ? 0 : (sInt ? 1 : 2);
    }
}

// ---------------- kernel 1: LN + QKV/gate/bias projection (R6-proven) -------
__global__ void __launch_bounds__(256, 1) prep_kernel(
    const float* __restrict__ z,
    const float* __restrict__ lnA, const float* __restrict__ lnB,
    const float* __restrict__ w_qkv, const float* __restrict__ w_bias,
    const float* __restrict__ w_gate)
{
    extern __shared__ float sm[];
    float* ws    = sm;                  // [NOUT][64]
    float* s_lnw = ws + NOUT * DD;
    float* s_lnb = s_lnw + DD;
    const int tid = threadIdx.x;

    const int swap = g_flags[0];
    const float* lnw = swap ? lnB : lnA;
    const float* lnb = swap ? lnA : lnB;

    for (int idx = tid; idx < 384 * DD; idx += 256) ws[idx]            = w_qkv[idx];
    for (int idx = tid; idx < 128 * DD; idx += 256) ws[384 * DD + idx] = w_gate[idx];
    for (int idx = tid; idx <   4 * DD; idx += 256) ws[512 * DD + idx] = w_bias[idx];
    if (tid < DD) { s_lnw[tid] = lnw[tid]; s_lnb[tid] = lnb[tid]; }
    __syncthreads();

    const int r0 = blockIdx.x * 2;
    const int c  = tid;

    ull h2[2][32];
    #pragma unroll
    for (int p = 0; p < 2; p++) {
        const float4* zp = (const float4*)(z + ((size_t)(r0 + p) * NN + c) * DD);
        float s = 0.f, sq = 0.f;
        #pragma unroll
        for (int k = 0; k < 16; k++) {
            float4 t = zp[k];
            s  += (t.x + t.y) + (t.z + t.w);
            sq += (t.x * t.x + t.y * t.y) + (t.z * t.z + t.w * t.w);
        }
        float mu  = s * (1.f / 64.f);
        float var = sq * (1.f / 64.f) - mu * mu;
        float rs  = rsqrtf(fmaxf(var, 0.f) + 1e-5f);
        #pragma unroll
        for (int k = 0; k < 16; k++) {             // second pass: L1 hits
            float4 t = zp[k];
            float a0 = (t.x - mu) * rs * s_lnw[4*k  ] + s_lnb[4*k  ];
            float a1 = (t.y - mu) * rs * s_lnw[4*k+1] + s_lnb[4*k+1];
            float a2 = (t.z - mu) * rs * s_lnw[4*k+2] + s_lnb[4*k+2];
            float a3 = (t.w - mu) * rs * s_lnw[4*k+3] + s_lnb[4*k+3];
            h2[p][2*k]   = pack2(a0, a1);
            h2[p][2*k+1] = pack2(a2, a3);
        }
    }

    for (int o = 0; o < NOUT; o++) {
        const ull* wr = (const ull*)(ws + o * DD);
        ull a0=0,a1=0,a2=0,a3=0, b0=0,b1=0,b2=0,b3=0;
        #pragma unroll
        for (int k = 0; k < 32; k += 4) {
            ull w0 = wr[k], w1 = wr[k+1], w2 = wr[k+2], w3 = wr[k+3];
            ffma2(a0, h2[0][k],   w0);  ffma2(b0, h2[1][k],   w0);
            ffma2(a1, h2[0][k+1], w1);  ffma2(b1, h2[1][k+1], w1);
            ffma2(a2, h2[0][k+2], w2);  ffma2(b2, h2[1][k+2], w2);
            ffma2(a3, h2[0][k+3], w3);  ffma2(b3, h2[1][k+3], w3);
        }
        float ra = (hsum2(a0) + hsum2(a1)) + (hsum2(a2) + hsum2(a3));
        float rb = (hsum2(b0) + hsum2(b1)) + (hsum2(b2) + hsum2(b3));

        if (o < 384) {
            int s   = o >> 7;          // 0=q 1=k 2=v
            int rem = o & 127;         // h*32 + d
            float* base = (s == 0) ? g_q : (s == 1) ? g_k : g_v;
            int hh = rem >> 5, d = rem & 31;
            base[(((r0    ) * NH + hh) * NN + c) * DHD + d] = ra;
            base[(((r0 + 1) * NH + hh) * NN + c) * DHD + d] = rb;
        } else if (o < 512) {
            int e = o - 384;
            g_gate[((size_t)(r0    ) * NN + c) * NINNER + e] = 1.f / (1.f + __expf(-ra));
            g_gate[((size_t)(r0 + 1) * NN + c) * NINNER + e] = 1.f / (1.f + __expf(-rb));
        } else {
            int hh = o - 512;
            g_bias[((size_t)hh * NN + r0    ) * NN + c] = ra;
            g_bias[((size_t)hh * NN + r0 + 1) * NN + c] = rb;
        }
    }
}

// ---------------- kernel 2: masked softmax attention + gate (QI=2, occ=3) ---
// block = (n, head), 128 threads; thread owns query rows tid and tid+128.
// K/V rows read via LDS.128 broadcast (16 per j). Per j: 16 LDS + 64 FFMA2.
// 3 blocks/SM for latency cover; jj unroll 2 keeps regs under the 170 cap.
__global__ void __launch_bounds__(128, 3) attn_kernel(const void* __restrict__ maskp)
{
    extern __shared__ float sm[];
    float* ks   = sm;                  // [256][32]
    float* vs   = ks + NN * DHD;       // [256][32]
    float* madd = vs + NN * DHD;       // [256]
    const int n  = blockIdx.x, hh = blockIdx.y;
    const int tid = threadIdx.x;

    {
        const float4* kg = (const float4*)(g_k + (size_t)((n * NH + hh) * NN) * DHD);
        const float4* vg = (const float4*)(g_v + (size_t)((n * NH + hh) * NN) * DHD);
        float4* ks4 = (float4*)ks; float4* vs4 = (float4*)vs;
        #pragma unroll
        for (int t = 0; t < 16; t++) {
            ks4[tid + 128 * t] = kg[tid + 128 * t];
            vs4[tid + 128 * t] = vg[tid + 128 * t];
        }
        const int mode = g_flags[1];
        #pragma unroll
        for (int p = 0; p < 2; p++) {
            int j = tid + 128 * p;
            bool on;
            if (mode == 2)      on = ((const unsigned char*)maskp)[n * NN + j] != 0;
            else if (mode == 1) on = ((const int*)maskp)[n * NN + j] != 0;
            else                on = ((const float*)maskp)[n * NN + j] != 0.f;
            madd[j] = on ? 0.f : -1e30f;
        }
    }
    __syncthreads();

    const int i0 = tid, i1 = tid + 128;
    ull q0[16], q1[16];                            // q * ATT_SCALE, packed
    {
        const float4* qg0 = (const float4*)(g_q + (size_t)((n * NH + hh) * NN + i0) * DHD);
        const float4* qg1 = (const float4*)(g_q + (size_t)((n * NH + hh) * NN + i1) * DHD);
        #pragma unroll
        for (int k = 0; k < 8; k++) {
            float4 t0 = qg0[k], t1 = qg1[k];
            q0[2*k]   = pack2(t0.x * ATT_SCALE, t0.y * ATT_SCALE);
            q0[2*k+1] = pack2(t0.z * ATT_SCALE, t0.w * ATT_SCALE);
            q1[2*k]   = pack2(t1.x * ATT_SCALE, t1.y * ATT_SCALE);
            q1[2*k+1] = pack2(t1.z * ATT_SCALE, t1.w * ATT_SCALE);
        }
    }
    const float* b0row = g_bias + (size_t)(hh * NN + i0) * NN;
    const float* b1row = g_bias + (size_t)(hh * NN + i1) * NN;

    ull acc0[16], acc1[16];
    #pragma unroll
    for (int k = 0; k < 16; k++) { acc0[k] = 0ull; acc1[k] = 0ull; }
    float ssum0 = 0.f, ssum1 = 0.f;

    for (int j0 = 0; j0 < NN; j0 += 2) {
        float2 bA = *(const float2*)(b0row + j0);
        float2 bB = *(const float2*)(b1row + j0);
        float2 m2 = *(const float2*)(madd + j0);
        float cb0[2] = {bA.x + m2.x, bA.y + m2.y};
        float cb1[2] = {bB.x + m2.x, bB.y + m2.y};
        #pragma unroll
        for (int jj = 0; jj < 2; jj++) {
            int j = j0 + jj;
            const ulonglong2* krow = (const ulonglong2*)(ks + j * DHD);  // LDS.128 b'cast
            ull d00=0, d01=0, d02=0, d03=0;
            ull d10=0, d11=0, d12=0, d13=0;
            #pragma unroll
            for (int k = 0; k < 4; k++) {
                ulonglong2 kA = krow[2*k], kB = krow[2*k+1];
                ffma2(d00, q0[4*k],   kA.x);  ffma2(d10, q1[4*k],   kA.x);
                ffma2(d01, q0[4*k+1], kA.y);  ffma2(d11, q1[4*k+1], kA.y);
                ffma2(d02, q0[4*k+2], kB.x);  ffma2(d12, q1[4*k+2], kB.x);
                ffma2(d03, q0[4*k+3], kB.y);  ffma2(d13, q1[4*k+3], kB.y);
            }
            d00 = addf2(d00, d01); d02 = addf2(d02, d03);
            d10 = addf2(d10, d11); d12 = addf2(d12, d13);
            float s0 = hsum2(addf2(d00, d02)) + cb0[jj];
            float s1 = hsum2(addf2(d10, d12)) + cb1[jj];
            float p0 = __expf(s0);
            float p1 = __expf(s1);
            ssum0 += p0;
            ssum1 += p1;
            ull p02 = pack2(p0, p0);
            ull p12 = pack2(p1, p1);
            const ulonglong2* vrow = (const ulonglong2*)(vs + j * DHD);  // LDS.128 b'cast
            #pragma unroll
            for (int k = 0; k < 8; k++) {
                ulonglong2 v2 = vrow[k];
                ffma2(acc0[2*k],   p02, v2.x);
                ffma2(acc0[2*k+1], p02, v2.y);
                ffma2(acc1[2*k],   p12, v2.x);
                ffma2(acc1[2*k+1], p12, v2.y);
            }
        }
    }

    {
        float inv0 = 1.f / ssum0;
        float inv1 = 1.f / ssum1;
        const float2* g0 = (const float2*)(g_gate + (size_t)(n * NN + i0) * NINNER + hh * DHD);
        const float2* g1 = (const float2*)(g_gate + (size_t)(n * NN + i1) * NINNER + hh * DHD);
        float2* a0p = (float2*)(g_ao + (size_t)(n * NN + i0) * NINNER + hh * DHD);
        float2* a1p = (float2*)(g_ao + (size_t)(n * NN + i1) * NINNER + hh * DHD);
        #pragma unroll
        for (int k = 0; k < 16; k++) {
            float2 a = unpack2(acc0[k]); float2 g = g0[k];
            float2 o; o.x = a.x * inv0 * g.x; o.y = a.y * inv0 * g.y;
            a0p[k] = o;
            float2 b = unpack2(acc1[k]); float2 h = g1[k];
            float2 u; u.x = b.x * inv1 * h.x; u.y = b.y * inv1 * h.y;
            a1p[k] = u;
        }
    }
}

// ---------------- kernel 3: (attn_out * gate) @ w_out^T (pipelined) ---------
// Register-tiled GEMM with software-pipelined double buffering: loads for
// e+1 issue before the FFMA2s of e, hiding the 29-cyc LDS latency behind the
// 16-FFMA2 compute body (the R13 profile showed issue=19%/fma=22%: scoreboard
// stalls, not pipe saturation).
#define OUT_P   128
#define US_LD   132   // pad: row stride, keeps 16B alignment (132*4 % 16 == 0)
__global__ void __launch_bounds__(256, 2) out_kernel(
    const float* __restrict__ w_out, float* __restrict__ out)
{
    extern __shared__ float sm[];
    float* ws_t = sm;                    // [128 e][64 d]
    float* us_t = ws_t + NINNER * DD;    // [128 e][132]
    const int tid = threadIdx.x;

    for (int idx = tid; idx < DD * NINNER; idx += 256) {
        int d = idx >> 7, e = idx & 127;
        ws_t[e * DD + d] = w_out[idx];                 // transpose store
    }
    const int p0 = blockIdx.x * OUT_P;
    for (int idx = tid; idx < OUT_P * NINNER / 4; idx += 256) {
        int p = idx >> 5, e0 = (idx & 31) * 4;         // float4 over e
        float4 a = *(const float4*)(g_ao + (size_t)(p0 + p) * NINNER + e0);
        us_t[(e0    ) * US_LD + p] = a.x;
        us_t[(e0 + 1) * US_LD + p] = a.y;
        us_t[(e0 + 2) * US_LD + p] = a.z;
        us_t[(e0 + 3) * US_LD + p] = a.w;
    }
    __syncthreads();

    const int warp = tid >> 5, lane = tid & 31;
    const int obase = warp * 8;                        // 8 outputs per warp
    const int pl = lane * 4;                           // 4 positions per lane
    ull acc[4][4];                                     // [pos][o-pair]
    #pragma unroll
    for (int p = 0; p < 4; p++)
        #pragma unroll
        for (int q = 0; q < 4; q++) acc[p][q] = 0ull;

    // ---- software pipeline: prefetch e, compute e-1 ----
    float4 u4 = *(const float4*)(us_t + pl);
    ulonglong2 wA = ((const ulonglong2*)(ws_t + obase))[0];
    ulonglong2 wB = ((const ulonglong2*)(ws_t + obase))[1];

    #pragma unroll 4
    for (int e = 0; e < NINNER; e++) {
        float4 uc = u4; ulonglong2 wAc = wA, wBc = wB;
        if (e + 1 < NINNER) {
            u4 = *(const float4*)(us_t + (e + 1) * US_LD + pl);
            const ulonglong2* wr = (const ulonglong2*)(ws_t + (e + 1) * DD + obase);
            wA = wr[0]; wB = wr[1];
        }
        float uu[4] = {uc.x, uc.y, uc.z, uc.w};
        #pragma unroll
        for (int p = 0; p < 4; p++) {
            ull up = pack2(uu[p], uu[p]);
            ffma2(acc[p][0], up, wAc.x);
            ffma2(acc[p][1], up, wAc.y);
            ffma2(acc[p][2], up, wBc.x);
            ffma2(acc[p][3], up, wBc.y);
        }
    }

    #pragma unroll
    for (int p = 0; p < 4; p++) {
        float2 c0 = unpack2(acc[p][0]), c1 = unpack2(acc[p][1]);
        float2 c2 = unpack2(acc[p][2]), c3 = unpack2(acc[p][3]);
        float* op = out + (size_t)(p0 + pl + p) * DD + obase;
        float4 f0 = {c0.x, c0.y, c1.x, c1.y};
        float4 f1 = {c2.x, c2.y, c3.x, c3.y};
        *(float4*)op       = f0;
        *(float4*)(op + 4) = f1;
    }
}

// ---------------- launch -----------------------------------------------------
extern "C" void kernel_launch(void* const* d_in, const int* in_sizes, int n_in,
                              void* d_out, int out_size)
{
    // Resolve inputs by ELEMENT count:
    //   z=4194304 (or 16777216 if bytes), mask=65536, w_qkv=24576, w_bias=256
    // Tie pairs: {ln_w, ln_b} both 64; {w_out, w_gate} both 8192.
    // Ordering scheme inferred from z's index (0 -> insertion order, else
    // alphabetical); ln pair additionally verified on-device (ln_w all-ones).
    const float* z = 0; const void* maskp = 0;
    const float *w_qkv = 0, *w_bias = 0;
    int idx_z = -1, i64[2] = {-1, -1}, n64 = 0, i8k[2] = {-1, -1}, n8k = 0;
    for (int i = 0; i < n_in; i++) {
        int s = in_sizes[i];
        if      (s == 4194304 || s == 16777216) { z = (const float*)d_in[i]; idx_z = i; }
        else if (s == 65536)    { maskp = d_in[i]; }
        else if (s == 24576)    { w_qkv = (const float*)d_in[i]; }
        else if (s == 256)      { w_bias = (const float*)d_in[i]; }
        else if (s == 64   && n64 < 2) { i64[n64++] = i; }
        else if (s == 8192 && n8k < 2) { i8k[n8k++] = i; }
    }
    const bool alpha = (idx_z != 0);
    const float* lnA    = (const float*)d_in[alpha ? i64[1] : i64[0]];  // presumed ln_w
    const float* lnB    = (const float*)d_in[alpha ? i64[0] : i64[1]];  // presumed ln_b
    const float* w_out  = (const float*)d_in[alpha ? i8k[1] : i8k[0]];
    const float* w_gate = (const float*)d_in[alpha ? i8k[0] : i8k[1]];
    float* out = (float*)d_out;

    const int smem_prep = (NOUT * DD + 2 * DD) * 4;            // 132608 B
    const int smem_attn = (2 * NN * DHD + NN) * 4;             //  66560 B
    const int smem_out  = (NINNER * DD + NINNER * US_LD) * 4;  // 100352 B
    cudaFuncSetAttribute(prep_kernel, cudaFuncAttributeMaxDynamicSharedMemorySize, smem_prep);
    cudaFuncSetAttribute(attn_kernel, cudaFuncAttributeMaxDynamicSharedMemorySize, smem_attn);
    cudaFuncSetAttribute(out_kernel,  cudaFuncAttributeMaxDynamicSharedMemorySize, smem_out);

    detect_kernel<<<1, 256>>>(lnA, lnB, (const unsigned int*)maskp);
    prep_kernel<<<128, 256, smem_prep>>>(z, lnA, lnB, w_qkv, w_bias, w_gate);
    attn_kernel<<<dim3(NN, NH), 128, smem_attn>>>(maskp);
    out_kernel<<<NN * NN / OUT_P, 256, smem_out>>>(w_out, out);
}

// round 15
// speedup vs baseline: 1.0541x; 1.0541x over previous
#include <cuda_runtime.h>

#define NN      256
#define DD      64
#define NH      4
#define DHD     32
#define NINNER  128
#define NOUT    516   // 384 qkv + 128 gate + 4 bias
#define ATT_SCALE 0.17677669529663687f  // 1/sqrt(32)

// ---------------- scratch (device globals: sanctioned, no runtime alloc) ----
__device__ float g_q   [NN*NH*NN*DHD];   // [n][h][c][d]
__device__ float g_k   [NN*NH*NN*DHD];
__device__ float g_v   [NN*NH*NN*DHD];
__device__ float g_gate[NN*NN*NINNER];   // [n][i][e], post-sigmoid
__device__ float g_bias[NH*NN*NN];       // [h][i][j]
__device__ float g_ao  [NN*NN*NINNER];   // attn-out * gate
__device__ int   g_flags[2];             // [0]=swap ln pair, [1]=mask mode (0=f32,1=i32,2=u8)

// ---------------- packed f32x2 helpers (FFMA2: 2 MACs per issue) ------------
typedef unsigned long long ull;

__device__ __forceinline__ void ffma2(ull& d, ull a, ull b) {
    asm volatile("fma.rn.f32x2 %0, %1, %2, %0;" : "+l"(d) : "l"(a), "l"(b));
}
__device__ __forceinline__ ull addf2(ull a, ull b) {
    ull r; asm("add.rn.f32x2 %0, %1, %2;" : "=l"(r) : "l"(a), "l"(b)); return r;
}
__device__ __forceinline__ ull pack2(float lo, float hi) {
    ull r; asm("mov.b64 %0, {%1, %2};" : "=l"(r) : "f"(lo), "f"(hi)); return r;
}
__device__ __forceinline__ float2 unpack2(ull v) {
    float2 r; asm("mov.b64 {%0, %1}, %2;" : "=f"(r.x), "=f"(r.y) : "l"(v)); return r;
}
__device__ __forceinline__ float hsum2(ull a) { float2 f = unpack2(a); return f.x + f.y; }

// ---------------- kernel 0: resolve input ambiguities on-device -------------
__global__ void detect_kernel(const float* __restrict__ lnA,
                              const float* __restrict__ lnB,
                              const unsigned int* __restrict__ mask_w)
{
    __shared__ int sA, sB, sFloat, sInt;
    if (threadIdx.x == 0) { sA = 1; sB = 1; sFloat = 1; sInt = 1; }
    __syncthreads();
    if (threadIdx.x < 64) {
        if (lnA[threadIdx.x] != 1.0f) atomicAnd(&sA, 0);
        if (lnB[threadIdx.x] != 1.0f) atomicAnd(&sB, 0);
    }
    for (int i = threadIdx.x; i < 4096; i += 256) {
        unsigned int w = mask_w[i];
        if (w != 0u && w != 0x3F800000u) atomicAnd(&sFloat, 0);
        if (w > 1u)                       atomicAnd(&sInt, 0);
    }
    __syncthreads();
    if (threadIdx.x == 0) {
        g_flags[0] = (!sA && sB) ? 1 : 0;
        g_flags[1] = sFloat ? 0 : (sInt ? 1 : 2);
    }
}

// ---------------- kernel 1: LN + QKV/gate/bias projection (R6-proven) -------
__global__ void __launch_bounds__(256, 1) prep_kernel(
    const float* __restrict__ z,
    const float* __restrict__ lnA, const float* __restrict__ lnB,
    const float* __restrict__ w_qkv, const float* __restrict__ w_bias,
    const float* __restrict__ w_gate)
{
    extern __shared__ float sm[];
    float* ws    = sm;                  // [NOUT][64]
    float* s_lnw = ws + NOUT * DD;
    float* s_lnb = s_lnw + DD;
    const int tid = threadIdx.x;

    const int swap = g_flags[0];
    const float* lnw = swap ? lnB : lnA;
    const float* lnb = swap ? lnA : lnB;

    for (int idx = tid; idx < 384 * DD; idx += 256) ws[idx]            = w_qkv[idx];
    for (int idx = tid; idx < 128 * DD; idx += 256) ws[384 * DD + idx] = w_gate[idx];
    for (int idx = tid; idx <   4 * DD; idx += 256) ws[512 * DD + idx] = w_bias[idx];
    if (tid < DD) { s_lnw[tid] = lnw[tid]; s_lnb[tid] = lnb[tid]; }
    __syncthreads();

    const int r0 = blockIdx.x * 2;
    const int c  = tid;

    ull h2[2][32];
    #pragma unroll
    for (int p = 0; p < 2; p++) {
        const float4* zp = (const float4*)(z + ((size_t)(r0 + p) * NN + c) * DD);
        float s = 0.f, sq = 0.f;
        #pragma unroll
        for (int k = 0; k < 16; k++) {
            float4 t = zp[k];
            s  += (t.x + t.y) + (t.z + t.w);
            sq += (t.x * t.x + t.y * t.y) + (t.z * t.z + t.w * t.w);
        }
        float mu  = s * (1.f / 64.f);
        float var = sq * (1.f / 64.f) - mu * mu;
        float rs  = rsqrtf(fmaxf(var, 0.f) + 1e-5f);
        #pragma unroll
        for (int k = 0; k < 16; k++) {             // second pass: L1 hits
            float4 t = zp[k];
            float a0 = (t.x - mu) * rs * s_lnw[4*k  ] + s_lnb[4*k  ];
            float a1 = (t.y - mu) * rs * s_lnw[4*k+1] + s_lnb[4*k+1];
            float a2 = (t.z - mu) * rs * s_lnw[4*k+2] + s_lnb[4*k+2];
            float a3 = (t.w - mu) * rs * s_lnw[4*k+3] + s_lnb[4*k+3];
            h2[p][2*k]   = pack2(a0, a1);
            h2[p][2*k+1] = pack2(a2, a3);
        }
    }

    for (int o = 0; o < NOUT; o++) {
        const ull* wr = (const ull*)(ws + o * DD);
        ull a0=0,a1=0,a2=0,a3=0, b0=0,b1=0,b2=0,b3=0;
        #pragma unroll
        for (int k = 0; k < 32; k += 4) {
            ull w0 = wr[k], w1 = wr[k+1], w2 = wr[k+2], w3 = wr[k+3];
            ffma2(a0, h2[0][k],   w0);  ffma2(b0, h2[1][k],   w0);
            ffma2(a1, h2[0][k+1], w1);  ffma2(b1, h2[1][k+1], w1);
            ffma2(a2, h2[0][k+2], w2);  ffma2(b2, h2[1][k+2], w2);
            ffma2(a3, h2[0][k+3], w3);  ffma2(b3, h2[1][k+3], w3);
        }
        float ra = (hsum2(a0) + hsum2(a1)) + (hsum2(a2) + hsum2(a3));
        float rb = (hsum2(b0) + hsum2(b1)) + (hsum2(b2) + hsum2(b3));

        if (o < 384) {
            int s   = o >> 7;          // 0=q 1=k 2=v
            int rem = o & 127;         // h*32 + d
            float* base = (s == 0) ? g_q : (s == 1) ? g_k : g_v;
            int hh = rem >> 5, d = rem & 31;
            base[(((r0    ) * NH + hh) * NN + c) * DHD + d] = ra;
            base[(((r0 + 1) * NH + hh) * NN + c) * DHD + d] = rb;
        } else if (o < 512) {
            int e = o - 384;
            g_gate[((size_t)(r0    ) * NN + c) * NINNER + e] = 1.f / (1.f + __expf(-ra));
            g_gate[((size_t)(r0 + 1) * NN + c) * NINNER + e] = 1.f / (1.f + __expf(-rb));
        } else {
            int hh = o - 512;
            g_bias[((size_t)hh * NN + r0    ) * NN + c] = ra;
            g_bias[((size_t)hh * NN + r0 + 1) * NN + c] = rb;
        }
    }
}

// ---------------- kernel 2: attention, QI=2, TWO HEADS PER BLOCK ------------
// block = (n, head-pair), 256 threads. Threads 0-127 handle head 2*hp,
// threads 128-255 handle head 2*hp+1; each thread owns query rows tidh and
// tidh+128 of its head. Inner loop is byte-identical to the R13-proven QI=2
// code (jj=4, LDS.64 broadcast). 16 warps/SM (occ 1, smem 133KB) doubles
// latency cover vs R13's 8; full 255-reg budget -> no spills.
__global__ void __launch_bounds__(256, 1) attn_kernel(const void* __restrict__ maskp)
{
    extern __shared__ float sm[];
    const int n   = blockIdx.x, hp = blockIdx.y;
    const int tid = threadIdx.x;
    const int half = tid >> 7, tidh = tid & 127;
    const int hh   = hp * 2 + half;
    float* ks   = sm + half * 16384;   // [256][32] this head's K
    float* vs   = ks + 8192;           // [256][32] this head's V
    float* madd = sm + 32768;          // [256], shared by both heads

    {
        const float4* kg = (const float4*)(g_k + (size_t)((n * NH + hh) * NN) * DHD);
        const float4* vg = (const float4*)(g_v + (size_t)((n * NH + hh) * NN) * DHD);
        float4* ks4 = (float4*)ks; float4* vs4 = (float4*)vs;
        #pragma unroll
        for (int t = 0; t < 16; t++) {
            ks4[tidh + 128 * t] = kg[tidh + 128 * t];
            vs4[tidh + 128 * t] = vg[tidh + 128 * t];
        }
        if (half == 0) {
            const int mode = g_flags[1];
            #pragma unroll
            for (int p = 0; p < 2; p++) {
                int j = tidh + 128 * p;
                bool on;
                if (mode == 2)      on = ((const unsigned char*)maskp)[n * NN + j] != 0;
                else if (mode == 1) on = ((const int*)maskp)[n * NN + j] != 0;
                else                on = ((const float*)maskp)[n * NN + j] != 0.f;
                madd[j] = on ? 0.f : -1e30f;
            }
        }
    }
    __syncthreads();

    const int i0 = tidh, i1 = tidh + 128;
    ull q0[16], q1[16];                            // q * ATT_SCALE, packed
    {
        const float4* qg0 = (const float4*)(g_q + (size_t)((n * NH + hh) * NN + i0) * DHD);
        const float4* qg1 = (const float4*)(g_q + (size_t)((n * NH + hh) * NN + i1) * DHD);
        #pragma unroll
        for (int k = 0; k < 8; k++) {
            float4 t0 = qg0[k], t1 = qg1[k];
            q0[2*k]   = pack2(t0.x * ATT_SCALE, t0.y * ATT_SCALE);
            q0[2*k+1] = pack2(t0.z * ATT_SCALE, t0.w * ATT_SCALE);
            q1[2*k]   = pack2(t1.x * ATT_SCALE, t1.y * ATT_SCALE);
            q1[2*k+1] = pack2(t1.z * ATT_SCALE, t1.w * ATT_SCALE);
        }
    }
    const float* b0row = g_bias + (size_t)(hh * NN + i0) * NN;
    const float* b1row = g_bias + (size_t)(hh * NN + i1) * NN;

    ull acc0[16], acc1[16];
    #pragma unroll
    for (int k = 0; k < 16; k++) { acc0[k] = 0ull; acc1[k] = 0ull; }
    float ssum0 = 0.f, ssum1 = 0.f;

    for (int j0 = 0; j0 < NN; j0 += 4) {
        float4 bA = *(const float4*)(b0row + j0);
        float4 bB = *(const float4*)(b1row + j0);
        float4 m4 = *(const float4*)(madd + j0);
        float cb0[4] = {bA.x + m4.x, bA.y + m4.y, bA.z + m4.z, bA.w + m4.w};
        float cb1[4] = {bB.x + m4.x, bB.y + m4.y, bB.z + m4.z, bB.w + m4.w};
        #pragma unroll
        for (int jj = 0; jj < 4; jj++) {
            int j = j0 + jj;
            const ull* krow = (const ull*)(ks + j * DHD);   // broadcast LDS.64
            ull d00=0, d01=0, d02=0, d03=0;
            ull d10=0, d11=0, d12=0, d13=0;
            #pragma unroll
            for (int k = 0; k < 16; k += 4) {
                ull k0 = krow[k], k1 = krow[k+1], k2 = krow[k+2], k3 = krow[k+3];
                ffma2(d00, q0[k],   k0);  ffma2(d10, q1[k],   k0);
                ffma2(d01, q0[k+1], k1);  ffma2(d11, q1[k+1], k1);
                ffma2(d02, q0[k+2], k2);  ffma2(d12, q1[k+2], k2);
                ffma2(d03, q0[k+3], k3);  ffma2(d13, q1[k+3], k3);
            }
            d00 = addf2(d00, d01); d02 = addf2(d02, d03);
            d10 = addf2(d10, d11); d12 = addf2(d12, d13);
            float s0 = hsum2(addf2(d00, d02)) + cb0[jj];
            float s1 = hsum2(addf2(d10, d12)) + cb1[jj];
            float p0 = __expf(s0);
            float p1 = __expf(s1);
            ssum0 += p0;
            ssum1 += p1;
            ull p02 = pack2(p0, p0);
            ull p12 = pack2(p1, p1);
            const ull* vrow = (const ull*)(vs + j * DHD);   // broadcast LDS.64
            #pragma unroll
            for (int k = 0; k < 16; k++) {
                ull vv = vrow[k];
                ffma2(acc0[k], p02, vv);
                ffma2(acc1[k], p12, vv);
            }
        }
    }

    {
        float inv0 = 1.f / ssum0;
        float inv1 = 1.f / ssum1;
        const float2* g0 = (const float2*)(g_gate + (size_t)(n * NN + i0) * NINNER + hh * DHD);
        const float2* g1 = (const float2*)(g_gate + (size_t)(n * NN + i1) * NINNER + hh * DHD);
        float2* a0p = (float2*)(g_ao + (size_t)(n * NN + i0) * NINNER + hh * DHD);
        float2* a1p = (float2*)(g_ao + (size_t)(n * NN + i1) * NINNER + hh * DHD);
        #pragma unroll
        for (int k = 0; k < 16; k++) {
            float2 a = unpack2(acc0[k]); float2 g = g0[k];
            float2 o; o.x = a.x * inv0 * g.x; o.y = a.y * inv0 * g.y;
            a0p[k] = o;
            float2 b = unpack2(acc1[k]); float2 h = g1[k];
            float2 u; u.x = b.x * inv1 * h.x; u.y = b.y * inv1 * h.y;
            a1p[k] = u;
        }
    }
}

// ---------------- kernel 3: (attn_out * gate) @ w_out^T (R13-proven) --------
// Register-tiled GEMM. Block = 128 positions, 8 warps; warp owns 8 outputs,
// lane owns 4 positions. Transposed smem: ws_t[e][64], us_t[e][132 pad].
#define OUT_P   128
#define US_LD   132   // pad: row stride, keeps 16B alignment (132*4 % 16 == 0)
__global__ void __launch_bounds__(256, 2) out_kernel(
    const float* __restrict__ w_out, float* __restrict__ out)
{
    extern __shared__ float sm[];
    float* ws_t = sm;                    // [128 e][64 d]
    float* us_t = ws_t + NINNER * DD;    // [128 e][132]
    const int tid = threadIdx.x;

    for (int idx = tid; idx < DD * NINNER; idx += 256) {
        int d = idx >> 7, e = idx & 127;
        ws_t[e * DD + d] = w_out[idx];                 // transpose store
    }
    const int p0 = blockIdx.x * OUT_P;
    for (int idx = tid; idx < OUT_P * NINNER / 4; idx += 256) {
        int p = idx >> 5, e0 = (idx & 31) * 4;         // float4 over e
        float4 a = *(const float4*)(g_ao + (size_t)(p0 + p) * NINNER + e0);
        us_t[(e0    ) * US_LD + p] = a.x;
        us_t[(e0 + 1) * US_LD + p] = a.y;
        us_t[(e0 + 2) * US_LD + p] = a.z;
        us_t[(e0 + 3) * US_LD + p] = a.w;
    }
    __syncthreads();

    const int warp = tid >> 5, lane = tid & 31;
    const int obase = warp * 8;                        // 8 outputs per warp
    const int pl = lane * 4;                           // 4 positions per lane
    ull acc[4][4];                                     // [pos][o-pair]
    #pragma unroll
    for (int p = 0; p < 4; p++)
        #pragma unroll
        for (int q = 0; q < 4; q++) acc[p][q] = 0ull;

    #pragma unroll 4
    for (int e = 0; e < NINNER; e++) {
        float4 u4 = *(const float4*)(us_t + e * US_LD + pl);          // lane-contig
        const ulonglong2* wr = (const ulonglong2*)(ws_t + e * DD + obase);
        ulonglong2 wA = wr[0], wB = wr[1];                            // broadcast
        float uu[4] = {u4.x, u4.y, u4.z, u4.w};
        #pragma unroll
        for (int p = 0; p < 4; p++) {
            ull up = pack2(uu[p], uu[p]);
            ffma2(acc[p][0], up, wA.x);
            ffma2(acc[p][1], up, wA.y);
            ffma2(acc[p][2], up, wB.x);
            ffma2(acc[p][3], up, wB.y);
        }
    }

    #pragma unroll
    for (int p = 0; p < 4; p++) {
        float2 c0 = unpack2(acc[p][0]), c1 = unpack2(acc[p][1]);
        float2 c2 = unpack2(acc[p][2]), c3 = unpack2(acc[p][3]);
        float* op = out + (size_t)(p0 + pl + p) * DD + obase;
        float4 f0 = {c0.x, c0.y, c1.x, c1.y};
        float4 f1 = {c2.x, c2.y, c3.x, c3.y};
        *(float4*)op       = f0;
        *(float4*)(op + 4) = f1;
    }
}

// ---------------- launch -----------------------------------------------------
extern "C" void kernel_launch(void* const* d_in, const int* in_sizes, int n_in,
                              void* d_out, int out_size)
{
    // Resolve inputs by ELEMENT count:
    //   z=4194304 (or 16777216 if bytes), mask=65536, w_qkv=24576, w_bias=256
    // Tie pairs: {ln_w, ln_b} both 64; {w_out, w_gate} both 8192.
    // Ordering scheme inferred from z's index (0 -> insertion order, else
    // alphabetical); ln pair additionally verified on-device (ln_w all-ones).
    const float* z = 0; const void* maskp = 0;
    const float *w_qkv = 0, *w_bias = 0;
    int idx_z = -1, i64[2] = {-1, -1}, n64 = 0, i8k[2] = {-1, -1}, n8k = 0;
    for (int i = 0; i < n_in; i++) {
        int s = in_sizes[i];
        if      (s == 4194304 || s == 16777216) { z = (const float*)d_in[i]; idx_z = i; }
        else if (s == 65536)    { maskp = d_in[i]; }
        else if (s == 24576)    { w_qkv = (const float*)d_in[i]; }
        else if (s == 256)      { w_bias = (const float*)d_in[i]; }
        else if (s == 64   && n64 < 2) { i64[n64++] = i; }
        else if (s == 8192 && n8k < 2) { i8k[n8k++] = i; }
    }
    const bool alpha = (idx_z != 0);
    const float* lnA    = (const float*)d_in[alpha ? i64[1] : i64[0]];  // presumed ln_w
    const float* lnB    = (const float*)d_in[alpha ? i64[0] : i64[1]];  // presumed ln_b
    const float* w_out  = (const float*)d_in[alpha ? i8k[1] : i8k[0]];
    const float* w_gate = (const float*)d_in[alpha ? i8k[0] : i8k[1]];
    float* out = (float*)d_out;

    const int smem_prep = (NOUT * DD + 2 * DD) * 4;            // 132608 B
    const int smem_attn = (4 * NN * DHD + NN) * 4;             // 132096 B (2 heads)
    const int smem_out  = (NINNER * DD + NINNER * US_LD) * 4;  // 100352 B
    cudaFuncSetAttribute(prep_kernel, cudaFuncAttributeMaxDynamicSharedMemorySize, smem_prep);
    cudaFuncSetAttribute(attn_kernel, cudaFuncAttributeMaxDynamicSharedMemorySize, smem_attn);
    cudaFuncSetAttribute(out_kernel,  cudaFuncAttributeMaxDynamicSharedMemorySize, smem_out);

    detect_kernel<<<1, 256>>>(lnA, lnB, (const unsigned int*)maskp);
    prep_kernel<<<128, 256, smem_prep>>>(z, lnA, lnB, w_qkv, w_bias, w_gate);
    attn_kernel<<<dim3(NN, NH/2), 256, smem_attn>>>(maskp);
    out_kernel<<<NN * NN / OUT_P, 256, smem_out>>>(w_out, out);
}

// round 16
// speedup vs baseline: 1.1288x; 1.0709x over previous
#include <cuda_runtime.h>

#define NN      256
#define DD      64
#define NH      4
#define DHD     32
#define NINNER  128
#define NOUT    516   // 384 qkv + 128 gate + 4 bias
#define ATT_SCALE 0.17677669529663687f  // 1/sqrt(32)
#define LOG2E     1.4426950408889634f
#define QSCALE    (0.17677669529663687f * 1.4426950408889634f)  // fold log2e into q

// ---------------- scratch (device globals: sanctioned, no runtime alloc) ----
__device__ float g_q   [NN*NH*NN*DHD];   // [n][h][c][d]
__device__ float g_k   [NN*NH*NN*DHD];
__device__ float g_v   [NN*NH*NN*DHD];
__device__ float g_gate[NN*NN*NINNER];   // [n][i][e], post-sigmoid
__device__ float g_bias[NH*NN*NN];       // [h][i][j]
__device__ float g_ao  [NN*NN*NINNER];   // attn-out * gate
__device__ int   g_flags[2];             // [0]=swap ln pair, [1]=mask mode (0=f32,1=i32,2=u8)

// ---------------- packed f32x2 helpers (FFMA2: 2 MACs per issue) ------------
typedef unsigned long long ull;

__device__ __forceinline__ void ffma2(ull& d, ull a, ull b) {
    asm volatile("fma.rn.f32x2 %0, %1, %2, %0;" : "+l"(d) : "l"(a), "l"(b));
}
__device__ __forceinline__ ull addf2(ull a, ull b) {
    ull r; asm("add.rn.f32x2 %0, %1, %2;" : "=l"(r) : "l"(a), "l"(b)); return r;
}
__device__ __forceinline__ ull pack2(float lo, float hi) {
    ull r; asm("mov.b64 %0, {%1, %2};" : "=l"(r) : "f"(lo), "f"(hi)); return r;
}
__device__ __forceinline__ float2 unpack2(ull v) {
    float2 r; asm("mov.b64 {%0, %1}, %2;" : "=f"(r.x), "=f"(r.y) : "l"(v)); return r;
}
__device__ __forceinline__ float hsum2(ull a) { float2 f = unpack2(a); return f.x + f.y; }

// ---------------- MUFU-free exp2: FMA/ALU pipes only ------------------------
// y is a base-2 exponent (log2e already folded upstream). Round via the
// 1.5*2^23 magic (RN), degree-5 poly for 2^frac (rel err <= 3.4e-6), exponent
// assembled with integer ops on the alu pipe. Clamp handles mask's -1e30.
__device__ __forceinline__ float fexp2(float y) {
    y = fmaxf(y, -125.0f);
    float m = y + 12582912.0f;          // RN to integer in low mantissa bits
    float r = m - 12582912.0f;          // rint(y)
    float f = y - r;                    // [-0.5, 0.5]
    float t = f * 0.6931471805599453f;  // frac * ln2
    float p = fmaf(t, 0.008333334f, 0.041666668f);
    p = fmaf(t, p, 0.16666667f);
    p = fmaf(t, p, 0.5f);
    p = fmaf(t, p, 1.0f);
    p = fmaf(t, p, 1.0f);
    int e = __float_as_int(m);
    return p * __int_as_float((e + 127) << 23);
}

// ---------------- kernel 0: resolve input ambiguities on-device -------------
__global__ void detect_kernel(const float* __restrict__ lnA,
                              const float* __restrict__ lnB,
                              const unsigned int* __restrict__ mask_w)
{
    __shared__ int sA, sB, sFloat, sInt;
    if (threadIdx.x == 0) { sA = 1; sB = 1; sFloat = 1; sInt = 1; }
    __syncthreads();
    if (threadIdx.x < 64) {
        if (lnA[threadIdx.x] != 1.0f) atomicAnd(&sA, 0);
        if (lnB[threadIdx.x] != 1.0f) atomicAnd(&sB, 0);
    }
    for (int i = threadIdx.x; i < 4096; i += 256) {
        unsigned int w = mask_w[i];
        if (w != 0u && w != 0x3F800000u) atomicAnd(&sFloat, 0);
        if (w > 1u)                       atomicAnd(&sInt, 0);
    }
    __syncthreads();
    if (threadIdx.x == 0) {
        g_flags[0] = (!sA && sB) ? 1 : 0;
        g_flags[1] = sFloat ? 0 : (sInt ? 1 : 2);
    }
}

// ---------------- kernel 1: LN + QKV/gate/bias projection (R6-proven) -------
__global__ void __launch_bounds__(256, 1) prep_kernel(
    const float* __restrict__ z,
    const float* __restrict__ lnA, const float* __restrict__ lnB,
    const float* __restrict__ w_qkv, const float* __restrict__ w_bias,
    const float* __restrict__ w_gate)
{
    extern __shared__ float sm[];
    float* ws    = sm;                  // [NOUT][64]
    float* s_lnw = ws + NOUT * DD;
    float* s_lnb = s_lnw + DD;
    const int tid = threadIdx.x;

    const int swap = g_flags[0];
    const float* lnw = swap ? lnB : lnA;
    const float* lnb = swap ? lnA : lnB;

    for (int idx = tid; idx < 384 * DD; idx += 256) ws[idx]            = w_qkv[idx];
    for (int idx = tid; idx < 128 * DD; idx += 256) ws[384 * DD + idx] = w_gate[idx];
    for (int idx = tid; idx <   4 * DD; idx += 256) ws[512 * DD + idx] = w_bias[idx];
    if (tid < DD) { s_lnw[tid] = lnw[tid]; s_lnb[tid] = lnb[tid]; }
    __syncthreads();

    const int r0 = blockIdx.x * 2;
    const int c  = tid;

    ull h2[2][32];
    #pragma unroll
    for (int p = 0; p < 2; p++) {
        const float4* zp = (const float4*)(z + ((size_t)(r0 + p) * NN + c) * DD);
        float s = 0.f, sq = 0.f;
        #pragma unroll
        for (int k = 0; k < 16; k++) {
            float4 t = zp[k];
            s  += (t.x + t.y) + (t.z + t.w);
            sq += (t.x * t.x + t.y * t.y) + (t.z * t.z + t.w * t.w);
        }
        float mu  = s * (1.f / 64.f);
        float var = sq * (1.f / 64.f) - mu * mu;
        float rs  = rsqrtf(fmaxf(var, 0.f) + 1e-5f);
        #pragma unroll
        for (int k = 0; k < 16; k++) {             // second pass: L1 hits
            float4 t = zp[k];
            float a0 = (t.x - mu) * rs * s_lnw[4*k  ] + s_lnb[4*k  ];
            float a1 = (t.y - mu) * rs * s_lnw[4*k+1] + s_lnb[4*k+1];
            float a2 = (t.z - mu) * rs * s_lnw[4*k+2] + s_lnb[4*k+2];
            float a3 = (t.w - mu) * rs * s_lnw[4*k+3] + s_lnb[4*k+3];
            h2[p][2*k]   = pack2(a0, a1);
            h2[p][2*k+1] = pack2(a2, a3);
        }
    }

    for (int o = 0; o < NOUT; o++) {
        const ull* wr = (const ull*)(ws + o * DD);
        ull a0=0,a1=0,a2=0,a3=0, b0=0,b1=0,b2=0,b3=0;
        #pragma unroll
        for (int k = 0; k < 32; k += 4) {
            ull w0 = wr[k], w1 = wr[k+1], w2 = wr[k+2], w3 = wr[k+3];
            ffma2(a0, h2[0][k],   w0);  ffma2(b0, h2[1][k],   w0);
            ffma2(a1, h2[0][k+1], w1);  ffma2(b1, h2[1][k+1], w1);
            ffma2(a2, h2[0][k+2], w2);  ffma2(b2, h2[1][k+2], w2);
            ffma2(a3, h2[0][k+3], w3);  ffma2(b3, h2[1][k+3], w3);
        }
        float ra = (hsum2(a0) + hsum2(a1)) + (hsum2(a2) + hsum2(a3));
        float rb = (hsum2(b0) + hsum2(b1)) + (hsum2(b2) + hsum2(b3));

        if (o < 384) {
            int s   = o >> 7;          // 0=q 1=k 2=v
            int rem = o & 127;         // h*32 + d
            float* base = (s == 0) ? g_q : (s == 1) ? g_k : g_v;
            int hh = rem >> 5, d = rem & 31;
            base[(((r0    ) * NH + hh) * NN + c) * DHD + d] = ra;
            base[(((r0 + 1) * NH + hh) * NN + c) * DHD + d] = rb;
        } else if (o < 512) {
            int e = o - 384;
            g_gate[((size_t)(r0    ) * NN + c) * NINNER + e] = 1.f / (1.f + __expf(-ra));
            g_gate[((size_t)(r0 + 1) * NN + c) * NINNER + e] = 1.f / (1.f + __expf(-rb));
        } else {
            int hh = o - 512;
            g_bias[((size_t)hh * NN + r0    ) * NN + c] = ra;
            g_bias[((size_t)hh * NN + r0 + 1) * NN + c] = rb;
        }
    }
}

// ---------------- kernel 2: attention (R13 structure + MUFU-free exp) -------
// block = (n, head), 128 threads; thread owns query rows tid and tid+128.
// Identical to the R13 winner except: q pre-scaled by ATT_SCALE*log2e, bias+
// mask scaled by log2e, and __expf replaced by fexp2 (FMA/ALU pipes only) —
// removing the 67M-exp MUFU serialization (~430us floor at rt_SMSP=8).
__global__ void __launch_bounds__(128, 2) attn_kernel(const void* __restrict__ maskp)
{
    extern __shared__ float sm[];
    float* ks   = sm;                  // [256][32]
    float* vs   = ks + NN * DHD;       // [256][32]
    float* madd = vs + NN * DHD;       // [256]
    const int n  = blockIdx.x, hh = blockIdx.y;
    const int tid = threadIdx.x;

    {
        const float4* kg = (const float4*)(g_k + (size_t)((n * NH + hh) * NN) * DHD);
        const float4* vg = (const float4*)(g_v + (size_t)((n * NH + hh) * NN) * DHD);
        float4* ks4 = (float4*)ks; float4* vs4 = (float4*)vs;
        #pragma unroll
        for (int t = 0; t < 16; t++) {
            ks4[tid + 128 * t] = kg[tid + 128 * t];
            vs4[tid + 128 * t] = vg[tid + 128 * t];
        }
        const int mode = g_flags[1];
        #pragma unroll
        for (int p = 0; p < 2; p++) {
            int j = tid + 128 * p;
            bool on;
            if (mode == 2)      on = ((const unsigned char*)maskp)[n * NN + j] != 0;
            else if (mode == 1) on = ((const int*)maskp)[n * NN + j] != 0;
            else                on = ((const float*)maskp)[n * NN + j] != 0.f;
            madd[j] = on ? 0.f : -1e30f;
        }
    }
    __syncthreads();

    const int i0 = tid, i1 = tid + 128;
    ull q0[16], q1[16];                            // q * ATT_SCALE * log2e, packed
    {
        const float4* qg0 = (const float4*)(g_q + (size_t)((n * NH + hh) * NN + i0) * DHD);
        const float4* qg1 = (const float4*)(g_q + (size_t)((n * NH + hh) * NN + i1) * DHD);
        #pragma unroll
        for (int k = 0; k < 8; k++) {
            float4 t0 = qg0[k], t1 = qg1[k];
            q0[2*k]   = pack2(t0.x * QSCALE, t0.y * QSCALE);
            q0[2*k+1] = pack2(t0.z * QSCALE, t0.w * QSCALE);
            q1[2*k]   = pack2(t1.x * QSCALE, t1.y * QSCALE);
            q1[2*k+1] = pack2(t1.z * QSCALE, t1.w * QSCALE);
        }
    }
    const float* b0row = g_bias + (size_t)(hh * NN + i0) * NN;
    const float* b1row = g_bias + (size_t)(hh * NN + i1) * NN;

    ull acc0[16], acc1[16];
    #pragma unroll
    for (int k = 0; k < 16; k++) { acc0[k] = 0ull; acc1[k] = 0ull; }
    float ssum0 = 0.f, ssum1 = 0.f;

    for (int j0 = 0; j0 < NN; j0 += 4) {
        float4 bA = *(const float4*)(b0row + j0);
        float4 bB = *(const float4*)(b1row + j0);
        float4 m4 = *(const float4*)(madd + j0);
        float cb0[4] = {(bA.x + m4.x) * LOG2E, (bA.y + m4.y) * LOG2E,
                        (bA.z + m4.z) * LOG2E, (bA.w + m4.w) * LOG2E};
        float cb1[4] = {(bB.x + m4.x) * LOG2E, (bB.y + m4.y) * LOG2E,
                        (bB.z + m4.z) * LOG2E, (bB.w + m4.w) * LOG2E};
        #pragma unroll
        for (int jj = 0; jj < 4; jj++) {
            int j = j0 + jj;
            const ull* krow = (const ull*)(ks + j * DHD);   // broadcast LDS.64
            ull d00=0, d01=0, d02=0, d03=0;
            ull d10=0, d11=0, d12=0, d13=0;
            #pragma unroll
            for (int k = 0; k < 16; k += 4) {
                ull k0 = krow[k], k1 = krow[k+1], k2 = krow[k+2], k3 = krow[k+3];
                ffma2(d00, q0[k],   k0);  ffma2(d10, q1[k],   k0);
                ffma2(d01, q0[k+1], k1);  ffma2(d11, q1[k+1], k1);
                ffma2(d02, q0[k+2], k2);  ffma2(d12, q1[k+2], k2);
                ffma2(d03, q0[k+3], k3);  ffma2(d13, q1[k+3], k3);
            }
            d00 = addf2(d00, d01); d02 = addf2(d02, d03);
            d10 = addf2(d10, d11); d12 = addf2(d12, d13);
            float s0 = hsum2(addf2(d00, d02)) + cb0[jj];
            float s1 = hsum2(addf2(d10, d12)) + cb1[jj];
            float p0 = fexp2(s0);
            float p1 = fexp2(s1);
            ssum0 += p0;
            ssum1 += p1;
            ull p02 = pack2(p0, p0);
            ull p12 = pack2(p1, p1);
            const ull* vrow = (const ull*)(vs + j * DHD);   // broadcast LDS.64
            #pragma unroll
            for (int k = 0; k < 16; k++) {
                ull vv = vrow[k];
                ffma2(acc0[k], p02, vv);
                ffma2(acc1[k], p12, vv);
            }
        }
    }

    {
        float inv0 = 1.f / ssum0;
        float inv1 = 1.f / ssum1;
        const float2* g0 = (const float2*)(g_gate + (size_t)(n * NN + i0) * NINNER + hh * DHD);
        const float2* g1 = (const float2*)(g_gate + (size_t)(n * NN + i1) * NINNER + hh * DHD);
        float2* a0p = (float2*)(g_ao + (size_t)(n * NN + i0) * NINNER + hh * DHD);
        float2* a1p = (float2*)(g_ao + (size_t)(n * NN + i1) * NINNER + hh * DHD);
        #pragma unroll
        for (int k = 0; k < 16; k++) {
            float2 a = unpack2(acc0[k]); float2 g = g0[k];
            float2 o; o.x = a.x * inv0 * g.x; o.y = a.y * inv0 * g.y;
            a0p[k] = o;
            float2 b = unpack2(acc1[k]); float2 h = g1[k];
            float2 u; u.x = b.x * inv1 * h.x; u.y = b.y * inv1 * h.y;
            a1p[k] = u;
        }
    }
}

// ---------------- kernel 3: (attn_out * gate) @ w_out^T (R13-proven) --------
#define OUT_P   128
#define US_LD   132   // pad: row stride, keeps 16B alignment (132*4 % 16 == 0)
__global__ void __launch_bounds__(256, 2) out_kernel(
    const float* __restrict__ w_out, float* __restrict__ out)
{
    extern __shared__ float sm[];
    float* ws_t = sm;                    // [128 e][64 d]
    float* us_t = ws_t + NINNER * DD;    // [128 e][132]
    const int tid = threadIdx.x;

    for (int idx = tid; idx < DD * NINNER; idx += 256) {
        int d = idx >> 7, e = idx & 127;
        ws_t[e * DD + d] = w_out[idx];                 // transpose store
    }
    const int p0 = blockIdx.x * OUT_P;
    for (int idx = tid; idx < OUT_P * NINNER / 4; idx += 256) {
        int p = idx >> 5, e0 = (idx & 31) * 4;         // float4 over e
        float4 a = *(const float4*)(g_ao + (size_t)(p0 + p) * NINNER + e0);
        us_t[(e0    ) * US_LD + p] = a.x;
        us_t[(e0 + 1) * US_LD + p] = a.y;
        us_t[(e0 + 2) * US_LD + p] = a.z;
        us_t[(e0 + 3) * US_LD + p] = a.w;
    }
    __syncthreads();

    const int warp = tid >> 5, lane = tid & 31;
    const int obase = warp * 8;                        // 8 outputs per warp
    const int pl = lane * 4;                           // 4 positions per lane
    ull acc[4][4];                                     // [pos][o-pair]
    #pragma unroll
    for (int p = 0; p < 4; p++)
        #pragma unroll
        for (int q = 0; q < 4; q++) acc[p][q] = 0ull;

    #pragma unroll 4
    for (int e = 0; e < NINNER; e++) {
        float4 u4 = *(const float4*)(us_t + e * US_LD + pl);          // lane-contig
        const ulonglong2* wr = (const ulonglong2*)(ws_t + e * DD + obase);
        ulonglong2 wA = wr[0], wB = wr[1];                            // broadcast
        float uu[4] = {u4.x, u4.y, u4.z, u4.w};
        #pragma unroll
        for (int p = 0; p < 4; p++) {
            ull up = pack2(uu[p], uu[p]);
            ffma2(acc[p][0], up, wA.x);
            ffma2(acc[p][1], up, wA.y);
            ffma2(acc[p][2], up, wB.x);
            ffma2(acc[p][3], up, wB.y);
        }
    }

    #pragma unroll
    for (int p = 0; p < 4; p++) {
        float2 c0 = unpack2(acc[p][0]), c1 = unpack2(acc[p][1]);
        float2 c2 = unpack2(acc[p][2]), c3 = unpack2(acc[p][3]);
        float* op = out + (size_t)(p0 + pl + p) * DD + obase;
        float4 f0 = {c0.x, c0.y, c1.x, c1.y};
        float4 f1 = {c2.x, c2.y, c3.x, c3.y};
        *(float4*)op       = f0;
        *(float4*)(op + 4) = f1;
    }
}

// ---------------- launch -----------------------------------------------------
extern "C" void kernel_launch(void* const* d_in, const int* in_sizes, int n_in,
                              void* d_out, int out_size)
{
    // Resolve inputs by ELEMENT count:
    //   z=4194304 (or 16777216 if bytes), mask=65536, w_qkv=24576, w_bias=256
    // Tie pairs: {ln_w, ln_b} both 64; {w_out, w_gate} both 8192.
    // Ordering scheme inferred from z's index (0 -> insertion order, else
    // alphabetical); ln pair additionally verified on-device (ln_w all-ones).
    const float* z = 0; const void* maskp = 0;
    const float *w_qkv = 0, *w_bias = 0;
    int idx_z = -1, i64[2] = {-1, -1}, n64 = 0, i8k[2] = {-1, -1}, n8k = 0;
    for (int i = 0; i < n_in; i++) {
        int s = in_sizes[i];
        if      (s == 4194304 || s == 16777216) { z = (const float*)d_in[i]; idx_z = i; }
        else if (s == 65536)    { maskp = d_in[i]; }
        else if (s == 24576)    { w_qkv = (const float*)d_in[i]; }
        else if (s == 256)      { w_bias = (const float*)d_in[i]; }
        else if (s == 64   && n64 < 2) { i64[n64++] = i; }
        else if (s == 8192 && n8k < 2) { i8k[n8k++] = i; }
    }
    const bool alpha = (idx_z != 0);
    const float* lnA    = (const float*)d_in[alpha ? i64[1] : i64[0]];  // presumed ln_w
    const float* lnB    = (const float*)d_in[alpha ? i64[0] : i64[1]];  // presumed ln_b
    const float* w_out  = (const float*)d_in[alpha ? i8k[1] : i8k[0]];
    const float* w_gate = (const float*)d_in[alpha ? i8k[0] : i8k[1]];
    float* out = (float*)d_out;

    const int smem_prep = (NOUT * DD + 2 * DD) * 4;            // 132608 B
    const int smem_attn = (2 * NN * DHD + NN) * 4;             //  66560 B
    const int smem_out  = (NINNER * DD + NINNER * US_LD) * 4;  // 100352 B
    cudaFuncSetAttribute(prep_kernel, cudaFuncAttributeMaxDynamicSharedMemorySize, smem_prep);
    cudaFuncSetAttribute(attn_kernel, cudaFuncAttributeMaxDynamicSharedMemorySize, smem_attn);
    cudaFuncSetAttribute(out_kernel,  cudaFuncAttributeMaxDynamicSharedMemorySize, smem_out);

    detect_kernel<<<1, 256>>>(lnA, lnB, (const unsigned int*)maskp);
    prep_kernel<<<128, 256, smem_prep>>>(z, lnA, lnB, w_qkv, w_bias, w_gate);
    attn_kernel<<<dim3(NN, NH), 128, smem_attn>>>(maskp);
    out_kernel<<<NN * NN / OUT_P, 256, smem_out>>>(w_out, out);
}

// round 17
// speedup vs baseline: 1.3220x; 1.1712x over previous
#include <cuda_runtime.h>

#define NN      256
#define DD      64
#define NH      4
#define DHD     32
#define NINNER  128
#define NOUT    516   // 384 qkv + 128 gate + 4 bias
#define ATT_SCALE 0.17677669529663687f  // 1/sqrt(32)

// ---------------- scratch (device globals: sanctioned, no runtime alloc) ----
__device__ float g_q   [NN*NH*NN*DHD];   // [n][h][c][d]
__device__ float g_k   [NN*NH*NN*DHD];
__device__ float g_v   [NN*NH*NN*DHD];
__device__ float g_gate[NN*NN*NINNER];   // [n][i][e], post-sigmoid
__device__ float g_bias[NH*NN*NN];       // [h][i][j]
__device__ float g_ao  [NN*NN*NINNER];   // attn-out * gate
__device__ int   g_flags[2];             // [0]=swap ln pair, [1]=mask mode (0=f32,1=i32,2=u8)

// ---------------- packed f32x2 helpers (FFMA2: 2 MACs per issue) ------------
typedef unsigned long long ull;

__device__ __forceinline__ void ffma2(ull& d, ull a, ull b) {
    asm volatile("fma.rn.f32x2 %0, %1, %2, %0;" : "+l"(d) : "l"(a), "l"(b));
}
__device__ __forceinline__ ull pack2(float lo, float hi) {
    ull r; asm("mov.b64 %0, {%1, %2};" : "=l"(r) : "f"(lo), "f"(hi)); return r;
}
__device__ __forceinline__ float2 unpack2(ull v) {
    float2 r; asm("mov.b64 {%0, %1}, %2;" : "=f"(r.x), "=f"(r.y) : "l"(v)); return r;
}
__device__ __forceinline__ float hsum2(ull a) { float2 f = unpack2(a); return f.x + f.y; }

// ---------------- tf32 mma helpers ------------------------------------------
__device__ __forceinline__ unsigned tf32r(float f) {
    unsigned r; asm("cvt.rna.tf32.f32 %0, %1;" : "=r"(r) : "f"(f)); return r;
}
__device__ __forceinline__ void mma_tf32(float& d0, float& d1, float& d2, float& d3,
                                         unsigned a0, unsigned a1, unsigned a2, unsigned a3,
                                         unsigned b0, unsigned b1) {
    asm volatile("mma.sync.aligned.m16n8k8.row.col.f32.tf32.tf32.f32 "
                 "{%0,%1,%2,%3}, {%4,%5,%6,%7}, {%8,%9}, {%0,%1,%2,%3};"
                 : "+f"(d0), "+f"(d1), "+f"(d2), "+f"(d3)
                 : "r"(a0), "r"(a1), "r"(a2), "r"(a3), "r"(b0), "r"(b1));
}

// ---------------- kernel 0: resolve input ambiguities on-device -------------
__global__ void detect_kernel(const float* __restrict__ lnA,
                              const float* __restrict__ lnB,
                              const unsigned int* __restrict__ mask_w)
{
    __shared__ int sA, sB, sFloat, sInt;
    if (threadIdx.x == 0) { sA = 1; sB = 1; sFloat = 1; sInt = 1; }
    __syncthreads();
    if (threadIdx.x < 64) {
        if (lnA[threadIdx.x] != 1.0f) atomicAnd(&sA, 0);
        if (lnB[threadIdx.x] != 1.0f) atomicAnd(&sB, 0);
    }
    for (int i = threadIdx.x; i < 4096; i += 256) {
        unsigned int w = mask_w[i];
        if (w != 0u && w != 0x3F800000u) atomicAnd(&sFloat, 0);
        if (w > 1u)                       atomicAnd(&sInt, 0);
    }
    __syncthreads();
    if (threadIdx.x == 0) {
        g_flags[0] = (!sA && sB) ? 1 : 0;
        g_flags[1] = sFloat ? 0 : (sInt ? 1 : 2);
    }
}

// ---------------- kernel 1: LN + QKV/gate/bias projection (R6-proven) -------
__global__ void __launch_bounds__(256, 1) prep_kernel(
    const float* __restrict__ z,
    const float* __restrict__ lnA, const float* __restrict__ lnB,
    const float* __restrict__ w_qkv, const float* __restrict__ w_bias,
    const float* __restrict__ w_gate)
{
    extern __shared__ float sm[];
    float* ws    = sm;                  // [NOUT][64]
    float* s_lnw = ws + NOUT * DD;
    float* s_lnb = s_lnw + DD;
    const int tid = threadIdx.x;

    const int swap = g_flags[0];
    const float* lnw = swap ? lnB : lnA;
    const float* lnb = swap ? lnA : lnB;

    for (int idx = tid; idx < 384 * DD; idx += 256) ws[idx]            = w_qkv[idx];
    for (int idx = tid; idx < 128 * DD; idx += 256) ws[384 * DD + idx] = w_gate[idx];
    for (int idx = tid; idx <   4 * DD; idx += 256) ws[512 * DD + idx] = w_bias[idx];
    if (tid < DD) { s_lnw[tid] = lnw[tid]; s_lnb[tid] = lnb[tid]; }
    __syncthreads();

    const int r0 = blockIdx.x * 2;
    const int c  = tid;

    ull h2[2][32];
    #pragma unroll
    for (int p = 0; p < 2; p++) {
        const float4* zp = (const float4*)(z + ((size_t)(r0 + p) * NN + c) * DD);
        float s = 0.f, sq = 0.f;
        #pragma unroll
        for (int k = 0; k < 16; k++) {
            float4 t = zp[k];
            s  += (t.x + t.y) + (t.z + t.w);
            sq += (t.x * t.x + t.y * t.y) + (t.z * t.z + t.w * t.w);
        }
        float mu  = s * (1.f / 64.f);
        float var = sq * (1.f / 64.f) - mu * mu;
        float rs  = rsqrtf(fmaxf(var, 0.f) + 1e-5f);
        #pragma unroll
        for (int k = 0; k < 16; k++) {             // second pass: L1 hits
            float4 t = zp[k];
            float a0 = (t.x - mu) * rs * s_lnw[4*k  ] + s_lnb[4*k  ];
            float a1 = (t.y - mu) * rs * s_lnw[4*k+1] + s_lnb[4*k+1];
            float a2 = (t.z - mu) * rs * s_lnw[4*k+2] + s_lnb[4*k+2];
            float a3 = (t.w - mu) * rs * s_lnw[4*k+3] + s_lnb[4*k+3];
            h2[p][2*k]   = pack2(a0, a1);
            h2[p][2*k+1] = pack2(a2, a3);
        }
    }

    for (int o = 0; o < NOUT; o++) {
        const ull* wr = (const ull*)(ws + o * DD);
        ull a0=0,a1=0,a2=0,a3=0, b0=0,b1=0,b2=0,b3=0;
        #pragma unroll
        for (int k = 0; k < 32; k += 4) {
            ull w0 = wr[k], w1 = wr[k+1], w2 = wr[k+2], w3 = wr[k+3];
            ffma2(a0, h2[0][k],   w0);  ffma2(b0, h2[1][k],   w0);
            ffma2(a1, h2[0][k+1], w1);  ffma2(b1, h2[1][k+1], w1);
            ffma2(a2, h2[0][k+2], w2);  ffma2(b2, h2[1][k+2], w2);
            ffma2(a3, h2[0][k+3], w3);  ffma2(b3, h2[1][k+3], w3);
        }
        float ra = (hsum2(a0) + hsum2(a1)) + (hsum2(a2) + hsum2(a3));
        float rb = (hsum2(b0) + hsum2(b1)) + (hsum2(b2) + hsum2(b3));

        if (o < 384) {
            int s   = o >> 7;          // 0=q 1=k 2=v
            int rem = o & 127;         // h*32 + d
            float* base = (s == 0) ? g_q : (s == 1) ? g_k : g_v;
            int hh = rem >> 5, d = rem & 31;
            base[(((r0    ) * NH + hh) * NN + c) * DHD + d] = ra;
            base[(((r0 + 1) * NH + hh) * NN + c) * DHD + d] = rb;
        } else if (o < 512) {
            int e = o - 384;
            g_gate[((size_t)(r0    ) * NN + c) * NINNER + e] = 1.f / (1.f + __expf(-ra));
            g_gate[((size_t)(r0 + 1) * NN + c) * NINNER + e] = 1.f / (1.f + __expf(-rb));
        } else {
            int hh = o - 512;
            g_bias[((size_t)hh * NN + r0    ) * NN + c] = ra;
            g_bias[((size_t)hh * NN + r0 + 1) * NN + c] = rb;
        }
    }
}

// ---------------- kernel 2: attention on TENSOR CORES (tf32 mma.sync) -------
// block = (n, head, row-half): 128 threads = 4 warps, warp owns M=32 query
// rows. K smem [256][36] (stride 36 -> B-frag bank = 4*(l/4)+l%4, conflict-
// free). V smem TRANSPOSED [32][260] (stride 260 = 4 mod 32 -> conflict-free).
// S = Q@K^T via m16n8k8 tf32 with bias preloaded into the C operand (fp32,
// exact); mask applied as {0,1} multiply after __expf; P shuffled from C-layout
// to A-layout within quads; O accumulated via tf32 mma; fixed-max softmax.
#define KSTR 36
#define VSTR 260
__global__ void __launch_bounds__(128) attn_kernel(const void* __restrict__ maskp)
{
    extern __shared__ float sm[];
    float* ks   = sm;                    // [256][KSTR]
    float* vt   = ks + NN * KSTR;        // [32][VSTR]  V transposed
    float* madd = vt + DHD * VSTR;       // [256] mask as {0,1}
    const int n = blockIdx.x, hh = blockIdx.y;
    const int tid = threadIdx.x;
    const int lane = tid & 31, warp = tid >> 5;
    const int i0 = blockIdx.z * 128 + warp * 32;   // warp's first query row

    // ---- stage K (tf32-rounded), V transposed (tf32-rounded), mask --------
    {
        const float4* kg = (const float4*)(g_k + (size_t)((n * NH + hh) * NN) * DHD);
        const float*  vg = g_v + (size_t)((n * NH + hh) * NN) * DHD;
        #pragma unroll
        for (int rr = 0; rr < 2; rr++) {
            int r = tid + rr * 128;
            #pragma unroll
            for (int c4 = 0; c4 < 8; c4++) {
                float4 kq = kg[r * 8 + c4];
                ks[r * KSTR + c4*4 + 0] = __uint_as_float(tf32r(kq.x));
                ks[r * KSTR + c4*4 + 1] = __uint_as_float(tf32r(kq.y));
                ks[r * KSTR + c4*4 + 2] = __uint_as_float(tf32r(kq.z));
                ks[r * KSTR + c4*4 + 3] = __uint_as_float(tf32r(kq.w));
            }
            const float* vrow = vg + (size_t)r * DHD;
            #pragma unroll
            for (int d = 0; d < DHD; d++)
                vt[d * VSTR + r] = __uint_as_float(tf32r(vrow[d]));
            const int mode = g_flags[1];
            bool on;
            if (mode == 2)      on = ((const unsigned char*)maskp)[n * NN + r] != 0;
            else if (mode == 1) on = ((const int*)maskp)[n * NN + r] != 0;
            else                on = ((const float*)maskp)[n * NN + r] != 0.f;
            madd[r] = on ? 1.f : 0.f;
        }
    }
    __syncthreads();

    // ---- Q A-fragments (pre-scaled, tf32), resident ------------------------
    unsigned qa[2][4][4];
    {
        const float* qb = g_q + (size_t)((n * NH + hh) * NN + i0) * DHD;
        #pragma unroll
        for (int mt = 0; mt < 2; mt++)
            #pragma unroll
            for (int kt = 0; kt < 4; kt++) {
                int r = mt * 16 + (lane >> 2), c = kt * 8 + (lane & 3);
                qa[mt][kt][0] = tf32r(qb[(size_t)(r    ) * DHD + c    ] * ATT_SCALE);
                qa[mt][kt][1] = tf32r(qb[(size_t)(r + 8) * DHD + c    ] * ATT_SCALE);
                qa[mt][kt][2] = tf32r(qb[(size_t)(r    ) * DHD + c + 4] * ATT_SCALE);
                qa[mt][kt][3] = tf32r(qb[(size_t)(r + 8) * DHD + c + 4] * ATT_SCALE);
            }
    }
    const float* brow = g_bias + ((size_t)hh * NN + i0) * NN;

    float oacc[2][4][4];
    #pragma unroll
    for (int mt = 0; mt < 2; mt++)
        #pragma unroll
        for (int nt = 0; nt < 4; nt++)
            #pragma unroll
            for (int q = 0; q < 4; q++) oacc[mt][nt][q] = 0.f;
    float rsum[2][2] = {{0.f, 0.f}, {0.f, 0.f}};

    const int srcA = (lane & ~3) | ((lane & 3) >> 1);
    const int srcB = srcA + 2;
    const bool oddc = lane & 1;

    for (int jt = 0; jt < NN; jt += 16) {
        // S tiles: C-init = bias (mask folded later as multiply)
        float s[2][2][4];
        #pragma unroll
        for (int mt = 0; mt < 2; mt++)
            #pragma unroll
            for (int nt = 0; nt < 2; nt++) {
                int r = mt * 16 + (lane >> 2);
                int j = jt + nt * 8 + 2 * (lane & 3);
                float2 b01 = *(const float2*)(brow + (size_t)r * NN + j);
                float2 b23 = *(const float2*)(brow + (size_t)(r + 8) * NN + j);
                s[mt][nt][0] = b01.x; s[mt][nt][1] = b01.y;
                s[mt][nt][2] = b23.x; s[mt][nt][3] = b23.y;
            }
        #pragma unroll
        for (int kt = 0; kt < 4; kt++) {
            unsigned kb[2][2];
            #pragma unroll
            for (int nt = 0; nt < 2; nt++) {
                int j = jt + nt * 8 + (lane >> 2);
                int d = kt * 8 + (lane & 3);
                kb[nt][0] = __float_as_uint(ks[j * KSTR + d]);
                kb[nt][1] = __float_as_uint(ks[j * KSTR + d + 4]);
            }
            #pragma unroll
            for (int mt = 0; mt < 2; mt++)
                #pragma unroll
                for (int nt = 0; nt < 2; nt++)
                    mma_tf32(s[mt][nt][0], s[mt][nt][1], s[mt][nt][2], s[mt][nt][3],
                             qa[mt][kt][0], qa[mt][kt][1], qa[mt][kt][2], qa[mt][kt][3],
                             kb[nt][0], kb[nt][1]);
        }
        // exp * mask, row-sum partials (C layout)
        float p[2][2][4];
        #pragma unroll
        for (int nt = 0; nt < 2; nt++) {
            float2 m01 = *(const float2*)(madd + jt + nt * 8 + 2 * (lane & 3));
            #pragma unroll
            for (int mt = 0; mt < 2; mt++) {
                float p0 = __expf(s[mt][nt][0]) * m01.x;
                float p1 = __expf(s[mt][nt][1]) * m01.y;
                float p2 = __expf(s[mt][nt][2]) * m01.x;
                float p3 = __expf(s[mt][nt][3]) * m01.y;
                p[mt][nt][0] = p0; p[mt][nt][1] = p1;
                p[mt][nt][2] = p2; p[mt][nt][3] = p3;
                rsum[mt][0] += p0 + p1;
                rsum[mt][1] += p2 + p3;
            }
        }
        // P: C-layout -> A-layout via quad shuffles, tf32-rounded
        unsigned pa[2][2][4];
        #pragma unroll
        for (int mt = 0; mt < 2; mt++)
            #pragma unroll
            for (int kt = 0; kt < 2; kt++) {
                float c0A = __shfl_sync(0xFFFFFFFFu, p[mt][kt][0], srcA);
                float c1A = __shfl_sync(0xFFFFFFFFu, p[mt][kt][1], srcA);
                float c2A = __shfl_sync(0xFFFFFFFFu, p[mt][kt][2], srcA);
                float c3A = __shfl_sync(0xFFFFFFFFu, p[mt][kt][3], srcA);
                float c0B = __shfl_sync(0xFFFFFFFFu, p[mt][kt][0], srcB);
                float c1B = __shfl_sync(0xFFFFFFFFu, p[mt][kt][1], srcB);
                float c2B = __shfl_sync(0xFFFFFFFFu, p[mt][kt][2], srcB);
                float c3B = __shfl_sync(0xFFFFFFFFu, p[mt][kt][3], srcB);
                pa[mt][kt][0] = tf32r(oddc ? c1A : c0A);
                pa[mt][kt][1] = tf32r(oddc ? c3A : c2A);
                pa[mt][kt][2] = tf32r(oddc ? c1B : c0B);
                pa[mt][kt][3] = tf32r(oddc ? c3B : c2B);
            }
        // O += P @ V  (V from transposed smem, conflict-free)
        #pragma unroll
        for (int kt = 0; kt < 2; kt++)
            #pragma unroll
            for (int nt = 0; nt < 4; nt++) {
                int j = jt + kt * 8 + (lane & 3);
                int d = nt * 8 + (lane >> 2);
                unsigned vb0 = __float_as_uint(vt[d * VSTR + j]);
                unsigned vb1 = __float_as_uint(vt[d * VSTR + j + 4]);
                #pragma unroll
                for (int mt = 0; mt < 2; mt++)
                    mma_tf32(oacc[mt][nt][0], oacc[mt][nt][1], oacc[mt][nt][2], oacc[mt][nt][3],
                             pa[mt][kt][0], pa[mt][kt][1], pa[mt][kt][2], pa[mt][kt][3],
                             vb0, vb1);
            }
    }

    // full row sums across the quad (each lane saw cols 2(l%4),+1 of each n8)
    #pragma unroll
    for (int mt = 0; mt < 2; mt++)
        #pragma unroll
        for (int h2 = 0; h2 < 2; h2++) {
            float v = rsum[mt][h2];
            v += __shfl_xor_sync(0xFFFFFFFFu, v, 1);
            v += __shfl_xor_sync(0xFFFFFFFFu, v, 2);
            rsum[mt][h2] = v;
        }

    // normalize, gate, store
    #pragma unroll
    for (int mt = 0; mt < 2; mt++) {
        float inv0 = 1.f / rsum[mt][0];
        float inv1 = 1.f / rsum[mt][1];
        #pragma unroll
        for (int nt = 0; nt < 4; nt++) {
            int i = i0 + mt * 16 + (lane >> 2);
            int e = hh * DHD + nt * 8 + 2 * (lane & 3);
            size_t b0 = ((size_t)(n * NN) + i    ) * NINNER + e;
            size_t b1 = ((size_t)(n * NN) + i + 8) * NINNER + e;
            float2 g0 = *(const float2*)(g_gate + b0);
            float2 g1 = *(const float2*)(g_gate + b1);
            float2 o0 = { oacc[mt][nt][0] * inv0 * g0.x, oacc[mt][nt][1] * inv0 * g0.y };
            float2 o1 = { oacc[mt][nt][2] * inv1 * g1.x, oacc[mt][nt][3] * inv1 * g1.y };
            *(float2*)(g_ao + b0) = o0;
            *(float2*)(g_ao + b1) = o1;
        }
    }
}

// ---------------- kernel 3: (attn_out * gate) @ w_out^T (R13-proven) --------
#define OUT_P   128
#define US_LD   132   // pad: row stride, keeps 16B alignment (132*4 % 16 == 0)
__global__ void __launch_bounds__(256, 2) out_kernel(
    const float* __restrict__ w_out, float* __restrict__ out)
{
    extern __shared__ float sm[];
    float* ws_t = sm;                    // [128 e][64 d]
    float* us_t = ws_t + NINNER * DD;    // [128 e][132]
    const int tid = threadIdx.x;

    for (int idx = tid; idx < DD * NINNER; idx += 256) {
        int d = idx >> 7, e = idx & 127;
        ws_t[e * DD + d] = w_out[idx];                 // transpose store
    }
    const int p0 = blockIdx.x * OUT_P;
    for (int idx = tid; idx < OUT_P * NINNER / 4; idx += 256) {
        int p = idx >> 5, e0 = (idx & 31) * 4;         // float4 over e
        float4 a = *(const float4*)(g_ao + (size_t)(p0 + p) * NINNER + e0);
        us_t[(e0    ) * US_LD + p] = a.x;
        us_t[(e0 + 1) * US_LD + p] = a.y;
        us_t[(e0 + 2) * US_LD + p] = a.z;
        us_t[(e0 + 3) * US_LD + p] = a.w;
    }
    __syncthreads();

    const int warp = tid >> 5, lane = tid & 31;
    const int obase = warp * 8;                        // 8 outputs per warp
    const int pl = lane * 4;                           // 4 positions per lane
    ull acc[4][4];                                     // [pos][o-pair]
    #pragma unroll
    for (int p = 0; p < 4; p++)
        #pragma unroll
        for (int q = 0; q < 4; q++) acc[p][q] = 0ull;

    #pragma unroll 4
    for (int e = 0; e < NINNER; e++) {
        float4 u4 = *(const float4*)(us_t + e * US_LD + pl);          // lane-contig
        const ulonglong2* wr = (const ulonglong2*)(ws_t + e * DD + obase);
        ulonglong2 wA = wr[0], wB = wr[1];                            // broadcast
        float uu[4] = {u4.x, u4.y, u4.z, u4.w};
        #pragma unroll
        for (int p = 0; p < 4; p++) {
            ull up = pack2(uu[p], uu[p]);
            ffma2(acc[p][0], up, wA.x);
            ffma2(acc[p][1], up, wA.y);
            ffma2(acc[p][2], up, wB.x);
            ffma2(acc[p][3], up, wB.y);
        }
    }

    #pragma unroll
    for (int p = 0; p < 4; p++) {
        float2 c0 = unpack2(acc[p][0]), c1 = unpack2(acc[p][1]);
        float2 c2 = unpack2(acc[p][2]), c3 = unpack2(acc[p][3]);
        float* op = out + (size_t)(p0 + pl + p) * DD + obase;
        float4 f0 = {c0.x, c0.y, c1.x, c1.y};
        float4 f1 = {c2.x, c2.y, c3.x, c3.y};
        *(float4*)op       = f0;
        *(float4*)(op + 4) = f1;
    }
}

// ---------------- launch -----------------------------------------------------
extern "C" void kernel_launch(void* const* d_in, const int* in_sizes, int n_in,
                              void* d_out, int out_size)
{
    // Resolve inputs by ELEMENT count:
    //   z=4194304 (or 16777216 if bytes), mask=65536, w_qkv=24576, w_bias=256
    // Tie pairs: {ln_w, ln_b} both 64; {w_out, w_gate} both 8192.
    // Ordering scheme inferred from z's index (0 -> insertion order, else
    // alphabetical); ln pair additionally verified on-device (ln_w all-ones).
    const float* z = 0; const void* maskp = 0;
    const float *w_qkv = 0, *w_bias = 0;
    int idx_z = -1, i64[2] = {-1, -1}, n64 = 0, i8k[2] = {-1, -1}, n8k = 0;
    for (int i = 0; i < n_in; i++) {
        int s = in_sizes[i];
        if      (s == 4194304 || s == 16777216) { z = (const float*)d_in[i]; idx_z = i; }
        else if (s == 65536)    { maskp = d_in[i]; }
        else if (s == 24576)    { w_qkv = (const float*)d_in[i]; }
        else if (s == 256)      { w_bias = (const float*)d_in[i]; }
        else if (s == 64   && n64 < 2) { i64[n64++] = i; }
        else if (s == 8192 && n8k < 2) { i8k[n8k++] = i; }
    }
    const bool alpha = (idx_z != 0);
    const float* lnA    = (const float*)d_in[alpha ? i64[1] : i64[0]];  // presumed ln_w
    const float* lnB    = (const float*)d_in[alpha ? i64[0] : i64[1]];  // presumed ln_b
    const float* w_out  = (const float*)d_in[alpha ? i8k[1] : i8k[0]];
    const float* w_gate = (const float*)d_in[alpha ? i8k[0] : i8k[1]];
    float* out = (float*)d_out;

    const int smem_prep = (NOUT * DD + 2 * DD) * 4;            // 132608 B
    const int smem_attn = (NN * KSTR + DHD * VSTR + NN) * 4;   //  71168 B
    const int smem_out  = (NINNER * DD + NINNER * US_LD) * 4;  // 100352 B
    cudaFuncSetAttribute(prep_kernel, cudaFuncAttributeMaxDynamicSharedMemorySize, smem_prep);
    cudaFuncSetAttribute(attn_kernel, cudaFuncAttributeMaxDynamicSharedMemorySize, smem_attn);
    cudaFuncSetAttribute(out_kernel,  cudaFuncAttributeMaxDynamicSharedMemorySize, smem_out);

    detect_kernel<<<1, 256>>>(lnA, lnB, (const unsigned int*)maskp);
    prep_kernel<<<128, 256, smem_prep>>>(z, lnA, lnB, w_qkv, w_bias, w_gate);
    attn_kernel<<<dim3(NN, NH, 2), 128, smem_attn>>>(maskp);
    out_kernel<<<NN * NN / OUT_P, 256, smem_out>>>(w_out, out);
}